// round 3
// baseline (speedup 1.0000x reference)
#include <cuda_runtime.h>
#include <math.h>

#define GN 4096
#define DN 256
#define TN 8192
#define NT 3

// ---------------- scratch (static device globals; no allocations) ----------
__device__ float g_dist[GN * TN];            // 128 MB distance matrix
__device__ float g_sq[TN];                   // squared norms of targets (gen||pos)
__device__ float g_rs[NT][GN];               // kernel row sums
__device__ float g_cs[NT][TN];               // kernel col sums
__device__ float g_hs[2][NT][GN];            // [0]=nrs (sum j<G), [1]=prs (sum j>=G)
__device__ float g_AB[2][NT][GN * DN];       // [0]=B=nk_neg@gen, [1]=A=nk_pos@pos
__device__ float g_vn[NT];                   // sum of squares of V_tau
__device__ float g_loss;                     // sum of squares of V_total

__constant__ float c_negc[NT] = {-50.0f, -20.0f, -5.0f};  // -1/tau

// ---------------- helpers --------------------------------------------------
__device__ __forceinline__ float block_reduce_256(float v, float* sh) {
#pragma unroll
    for (int o = 16; o; o >>= 1) v += __shfl_xor_sync(0xffffffffu, v, o);
    int w = threadIdx.x >> 5;
    if ((threadIdx.x & 31) == 0) sh[w] = v;
    __syncthreads();
    if (threadIdx.x < 32) {
        v = (threadIdx.x < 8) ? sh[threadIdx.x] : 0.0f;
#pragma unroll
        for (int o = 4; o; o >>= 1) v += __shfl_xor_sync(0xffffffffu, v, o);
    }
    return v;  // valid in thread 0
}

// ---------------- kernels --------------------------------------------------

__global__ void k_zero() {
    int idx = blockIdx.x * 256 + threadIdx.x;          // grid 96*256 = 24576
    if (idx < NT * GN)     (&g_rs[0][0])[idx] = 0.0f;
    if (idx < NT * TN)     (&g_cs[0][0])[idx] = 0.0f;
    if (idx < 2 * NT * GN) (&g_hs[0][0][0])[idx] = 0.0f;
    if (idx < NT)          g_vn[idx] = 0.0f;
    if (idx == 0)          g_loss = 0.0f;
}

// squared norms of all 8192 target rows (first 4096 = gen, rest = pos)
__global__ void k_sq(const float* __restrict__ gen, const float* __restrict__ pos) {
    int gw = (blockIdx.x * blockDim.x + threadIdx.x) >> 5;
    int lane = threadIdx.x & 31;
    if (gw >= TN) return;
    const float* rowp = (gw < GN) ? (gen + (size_t)gw * DN) : (pos + (size_t)(gw - GN) * DN);
    const float4* r4 = (const float4*)rowp;
    float4 a = r4[lane];
    float4 b = r4[lane + 32];
    float s = a.x * a.x + a.y * a.y + a.z * a.z + a.w * a.w +
              b.x * b.x + b.y * b.y + b.z * b.z + b.w * b.w;
#pragma unroll
    for (int o = 16; o; o >>= 1) s += __shfl_xor_sync(0xffffffffu, s, o);
    if (lane == 0) g_sq[gw] = s;
}

// dist[i][j] = sqrt(max(|gi|^2 + |tj|^2 - 2 gi.tj, 0)) / 16  (diag -> 1e6)
// 128x128 tile, 8x8 per thread, K-chunks of 16
__global__ __launch_bounds__(256) void k_dist(const float* __restrict__ gen,
                                              const float* __restrict__ pos) {
    __shared__ float As[16][128];
    __shared__ float Bs[16][128];
    const int bi = blockIdx.y * 128;
    const int bj = blockIdx.x * 128;
    const int tid = threadIdx.x;
    const int tx = tid & 15, ty = tid >> 4;
    const int lr = tid >> 1;
    const int lk = (tid & 1) * 8;
    const float* amat = gen + (size_t)(bi + lr) * DN + lk;
    const float* bmat = ((bj < GN) ? gen + (size_t)(bj + lr) * DN
                                   : pos + (size_t)(bj - GN + lr) * DN) + lk;
    float acc[8][8];
#pragma unroll
    for (int i = 0; i < 8; i++)
#pragma unroll
        for (int j = 0; j < 8; j++) acc[i][j] = 0.0f;

    for (int k0 = 0; k0 < DN; k0 += 16) {
        float4 a0 = *(const float4*)(amat + k0);
        float4 a1 = *(const float4*)(amat + k0 + 4);
        float4 b0 = *(const float4*)(bmat + k0);
        float4 b1 = *(const float4*)(bmat + k0 + 4);
        __syncthreads();
        As[lk + 0][lr] = a0.x; As[lk + 1][lr] = a0.y; As[lk + 2][lr] = a0.z; As[lk + 3][lr] = a0.w;
        As[lk + 4][lr] = a1.x; As[lk + 5][lr] = a1.y; As[lk + 6][lr] = a1.z; As[lk + 7][lr] = a1.w;
        Bs[lk + 0][lr] = b0.x; Bs[lk + 1][lr] = b0.y; Bs[lk + 2][lr] = b0.z; Bs[lk + 3][lr] = b0.w;
        Bs[lk + 4][lr] = b1.x; Bs[lk + 5][lr] = b1.y; Bs[lk + 6][lr] = b1.z; Bs[lk + 7][lr] = b1.w;
        __syncthreads();
#pragma unroll
        for (int kk = 0; kk < 16; kk++) {
            float af[8], bf[8];
            *(float4*)(af)     = *(const float4*)&As[kk][ty * 8];
            *(float4*)(af + 4) = *(const float4*)&As[kk][ty * 8 + 4];
            *(float4*)(bf)     = *(const float4*)&Bs[kk][tx * 8];
            *(float4*)(bf + 4) = *(const float4*)&Bs[kk][tx * 8 + 4];
#pragma unroll
            for (int i = 0; i < 8; i++)
#pragma unroll
                for (int j = 0; j < 8; j++) acc[i][j] = fmaf(af[i], bf[j], acc[i][j]);
        }
    }

    float sj[8];
#pragma unroll
    for (int j = 0; j < 8; j++) sj[j] = g_sq[bj + tx * 8 + j];
#pragma unroll
    for (int i = 0; i < 8; i++) {
        int gi = bi + ty * 8 + i;
        float si = g_sq[gi];
        float o[8];
#pragma unroll
        for (int j = 0; j < 8; j++) {
            int gj = bj + tx * 8 + j;
            float d2 = si + sj[j] - 2.0f * acc[i][j];
            float d = sqrtf(fmaxf(d2, 0.0f)) * 0.0625f;  // / sqrt(256)
            if (gi == gj) d = 1.0e6f;
            o[j] = d;
        }
        float* dst = g_dist + (size_t)gi * TN + bj + tx * 8;
        *(float4*)dst       = make_float4(o[0], o[1], o[2], o[3]);
        *(float4*)(dst + 4) = make_float4(o[4], o[5], o[6], o[7]);
    }
}

// row sums of exp(-d/tau) for the 3 temps; one warp per row
__global__ void k_rowsum() {
    int gw = (blockIdx.x * blockDim.x + threadIdx.x) >> 5;
    int lane = threadIdx.x & 31;
    if (gw >= GN) return;
    const float* row = g_dist + (size_t)gw * TN;
    float s0 = 0.0f, s1 = 0.0f, s2 = 0.0f;
    for (int j = lane * 4; j < TN; j += 128) {
        float4 d = *(const float4*)(row + j);
        s0 += __expf(-50.0f * d.x) + __expf(-50.0f * d.y) + __expf(-50.0f * d.z) + __expf(-50.0f * d.w);
        s1 += __expf(-20.0f * d.x) + __expf(-20.0f * d.y) + __expf(-20.0f * d.z) + __expf(-20.0f * d.w);
        s2 += __expf(-5.0f  * d.x) + __expf(-5.0f  * d.y) + __expf(-5.0f  * d.z) + __expf(-5.0f  * d.w);
    }
#pragma unroll
    for (int o = 16; o; o >>= 1) {
        s0 += __shfl_xor_sync(0xffffffffu, s0, o);
        s1 += __shfl_xor_sync(0xffffffffu, s1, o);
        s2 += __shfl_xor_sync(0xffffffffu, s2, o);
    }
    if (lane == 0) { g_rs[0][gw] = s0; g_rs[1][gw] = s1; g_rs[2][gw] = s2; }
}

// col sums; thread per column, 256-row chunks, atomic accumulate
__global__ void k_colsum() {
    int j = blockIdx.x * 256 + threadIdx.x;
    int r0 = blockIdx.y * 256;
    const float* p = g_dist + (size_t)r0 * TN + j;
    float s0 = 0.0f, s1 = 0.0f, s2 = 0.0f;
    for (int r = 0; r < 256; r++) {
        float d = p[(size_t)r * TN];
        s0 += __expf(-50.0f * d);
        s1 += __expf(-20.0f * d);
        s2 += __expf(-5.0f  * d);
    }
    atomicAdd(&g_cs[0][j], s0);
    atomicAdd(&g_cs[1][j], s1);
    atomicAdd(&g_cs[2][j], s2);
}

// main weighted GEMM: for (tau,h) compute AB[h][tau] = nk_half @ tmat and
// hs[h][tau][i] = row sums of nk over the half.  z = tau*2 + h.
__global__ __launch_bounds__(256) void k_main(const float* __restrict__ gen,
                                              const float* __restrict__ pos) {
    __shared__ float sW[16][128];
    __shared__ float sT[16][128];
    __shared__ float sSum[256];
    const int tau = blockIdx.z >> 1;
    const int h = blockIdx.z & 1;
    const int bi = blockIdx.y * 128;
    const int bc = blockIdx.x * 128;
    const int jbase = h * GN;
    const float* tmat = h ? pos : gen;
    const float cexp = c_negc[tau];
    const int tid = threadIdx.x;
    const int tx = tid & 15, ty = tid >> 4;
    const int lr = tid >> 1;
    const int lk = (tid & 1) * 8;
    const int ttr = tid & 15;
    const int tcc = (tid >> 4) * 8;
    const float rsv = g_rs[tau][bi + lr];
    float rsum = 0.0f;
    float acc[8][8];
#pragma unroll
    for (int i = 0; i < 8; i++)
#pragma unroll
        for (int j = 0; j < 8; j++) acc[i][j] = 0.0f;

    const float* dbase = g_dist + (size_t)(bi + lr) * TN + jbase + lk;
    for (int j0 = 0; j0 < GN; j0 += 16) {
        float4 d0 = *(const float4*)(dbase + j0);
        float4 d1 = *(const float4*)(dbase + j0 + 4);
        const float* trow = tmat + (size_t)(j0 + ttr) * DN + bc + tcc;
        float4 t0 = *(const float4*)trow;
        float4 t1 = *(const float4*)(trow + 4);
        float w[8];
        {
            float dd[8] = {d0.x, d0.y, d0.z, d0.w, d1.x, d1.y, d1.z, d1.w};
            const float* csp = &g_cs[tau][jbase + j0 + lk];
            float4 c0 = *(const float4*)(csp);
            float4 c1 = *(const float4*)(csp + 4);
            float cc8[8] = {c0.x, c0.y, c0.z, c0.w, c1.x, c1.y, c1.z, c1.w};
#pragma unroll
            for (int q = 0; q < 8; q++) {
                float kv = __expf(cexp * dd[q]);
                float p2 = fmaxf(rsv * cc8[q], 1e-12f);   // EXACT reference clamp semantics
                float wv = kv * rsqrtf(p2);
                w[q] = wv;
                rsum += wv;
            }
        }
        __syncthreads();
#pragma unroll
        for (int q = 0; q < 8; q++) sW[lk + q][lr] = w[q];
        *(float4*)&sT[ttr][tcc]     = t0;
        *(float4*)&sT[ttr][tcc + 4] = t1;
        __syncthreads();
#pragma unroll
        for (int kk = 0; kk < 16; kk++) {
            float af[8], bf[8];
            *(float4*)(af)     = *(const float4*)&sW[kk][ty * 8];
            *(float4*)(af + 4) = *(const float4*)&sW[kk][ty * 8 + 4];
            *(float4*)(bf)     = *(const float4*)&sT[kk][tx * 8];
            *(float4*)(bf + 4) = *(const float4*)&sT[kk][tx * 8 + 4];
#pragma unroll
            for (int i = 0; i < 8; i++)
#pragma unroll
                for (int j = 0; j < 8; j++) acc[i][j] = fmaf(af[i], bf[j], acc[i][j]);
        }
    }

    float* out = &g_AB[h][tau][0];
#pragma unroll
    for (int i = 0; i < 8; i++) {
        int gi = bi + ty * 8 + i;
        float* dst = out + (size_t)gi * DN + bc + tx * 8;
        *(float4*)dst       = make_float4(acc[i][0], acc[i][1], acc[i][2], acc[i][3]);
        *(float4*)(dst + 4) = make_float4(acc[i][4], acc[i][5], acc[i][6], acc[i][7]);
    }

    if (blockIdx.x == 0) {
        sSum[tid] = rsum;
        __syncthreads();
        if (tid < 128) g_hs[h][tau][bi + tid] = sSum[2 * tid] + sSum[2 * tid + 1];
    }
}

// sum of squares of V_tau = hs0*A - hs1*B
__global__ void k_vnorm() {
    __shared__ float sh[8];
    const int tau = blockIdx.y;
    float s = 0.0f;
    for (int idx = blockIdx.x * blockDim.x + threadIdx.x; idx < GN * DN;
         idx += gridDim.x * blockDim.x) {
        int i = idx >> 8;
        float v = g_hs[0][tau][i] * g_AB[1][tau][idx] - g_hs[1][tau][i] * g_AB[0][tau][idx];
        s += v * v;
    }
    s = block_reduce_256(s, sh);
    if (threadIdx.x == 0) atomicAdd(&g_vn[tau], s);
}

// loss partial sums: mean(V_total^2)
__global__ void k_loss() {
    __shared__ float sh[8];
    float inv[NT];
#pragma unroll
    for (int t = 0; t < NT; t++) {
        float m = g_vn[t] * (1.0f / 1048576.0f);
        inv[t] = 1.0f / (sqrtf(m + 1e-8f) + 1e-8f);
    }
    float s = 0.0f;
    for (int idx = blockIdx.x * blockDim.x + threadIdx.x; idx < GN * DN;
         idx += gridDim.x * blockDim.x) {
        int i = idx >> 8;
        float v = 0.0f;
#pragma unroll
        for (int t = 0; t < NT; t++) {
            float vt = g_hs[0][t][i] * g_AB[1][t][idx] - g_hs[1][t][i] * g_AB[0][t][idx];
            v += vt * inv[t];
        }
        s += v * v;
    }
    s = block_reduce_256(s, sh);
    if (threadIdx.x == 0) atomicAdd(&g_loss, s);
}

__global__ void k_final(float* __restrict__ out) {
    out[0] = g_loss * (1.0f / 1048576.0f);
}

// ---------------- launch ----------------------------------------------------
extern "C" void kernel_launch(void* const* d_in, const int* in_sizes, int n_in,
                              void* d_out, int out_size) {
    const float* gen = (const float*)d_in[0];
    const float* pos = (const float*)d_in[1];
    float* out = (float*)d_out;
    (void)in_sizes; (void)n_in; (void)out_size;

    k_zero<<<96, 256>>>();
    k_sq<<<TN * 32 / 256, 256>>>(gen, pos);

    dim3 gdist(TN / 128, GN / 128);       // (64, 32)
    k_dist<<<gdist, 256>>>(gen, pos);

    k_rowsum<<<GN * 32 / 256, 256>>>();   // 512 blocks
    dim3 gcol(TN / 256, 16);              // (32, 16)
    k_colsum<<<gcol, 256>>>();

    dim3 gmain(2, GN / 128, 2 * NT);      // (2, 32, 6)
    k_main<<<gmain, 256>>>(gen, pos);

    dim3 gv(256, NT);
    k_vnorm<<<gv, 256>>>();
    k_loss<<<256, 256>>>();
    k_final<<<1, 1>>>(out);
}